// round 5
// baseline (speedup 1.0000x reference)
#include <cuda_runtime.h>
#include <math.h>

#define D_IN 768
#define H    256
#define NB   64
#define NT   512
#define BT   (NB*NT)    // 32768
#define G3   768        // 3*H
#define NCTA 128        // scan CTAs (single wave)

// ---------------- scratch (static device arrays: allowed) ----------------
__device__ float g_gi1[BT * (size_t)G3];          // 96 MB, time-major rows (t*64+b)
__device__ float g_gi2[BT * (size_t)G3];          // 96 MB
__device__ float g_h1tm[BT * (size_t)H];          // 32 MB, time-major h1
__device__ float g_hbuf[2][NB * H];               // double-buffered recurrent state
__device__ unsigned g_barcnt;
__device__ volatile unsigned g_bargen;

// ---------------- init ----------------
__global__ void init_kernel() {
    int tid = blockIdx.x * blockDim.x + threadIdx.x;
    int nth = gridDim.x * blockDim.x;
    for (int i = tid; i < 2 * NB * H; i += nth)
        ((float*)g_hbuf)[i] = 0.0f;
    if (tid == 0) { g_barcnt = 0u; g_bargen = 0u; }
}

// ---------------- fp32 tiled GEMM ----------------
// C[32768 x 768](time-major-or-identity rows) = A[32768 x K](lda) @ W[K x 768] (+bias) (+=C)
#define BM 128
#define BN 128
#define BKG 16

__global__ void __launch_bounds__(256, 2)
gemm_kernel(const float* __restrict__ A, int lda, int K,
            const float* __restrict__ W, const float* __restrict__ bias,
            float* __restrict__ C, int acc, int cmap)
{
    __shared__ float As[BKG][BM + 4];
    __shared__ float Bs[BKG][BN];

    const int tid  = threadIdx.x;
    const int row0 = blockIdx.y * BM;
    const int col0 = blockIdx.x * BN;
    const int tx   = tid & 15;
    const int ty   = tid >> 4;

    float accm[8][8];
#pragma unroll
    for (int i = 0; i < 8; i++)
#pragma unroll
        for (int j = 0; j < 8; j++) accm[i][j] = 0.0f;

    const int arow0 = tid >> 2;          // 0..63 (+64)
    const int ak0   = (tid & 3) << 2;    // 0,4,8,12
    const int brow0 = tid >> 5;          // 0..7 (+8)
    const int bc0   = (tid & 31) << 2;   // 0..124

    for (int kk = 0; kk < K; kk += BKG) {
#pragma unroll
        for (int L = 0; L < 2; L++) {
            int ar = arow0 + L * 64;
            float4 av = *(const float4*)(A + (size_t)(row0 + ar) * lda + kk + ak0);
            As[ak0 + 0][ar] = av.x;
            As[ak0 + 1][ar] = av.y;
            As[ak0 + 2][ar] = av.z;
            As[ak0 + 3][ar] = av.w;
            int br = brow0 + L * 8;
            *(float4*)(&Bs[br][bc0]) =
                *(const float4*)(W + (size_t)(kk + br) * G3 + col0 + bc0);
        }
        __syncthreads();
#pragma unroll
        for (int k = 0; k < BKG; k++) {
            float a[8], b[8];
            *(float4*)&a[0] = *(const float4*)&As[k][ty * 8];
            *(float4*)&a[4] = *(const float4*)&As[k][ty * 8 + 4];
            *(float4*)&b[0] = *(const float4*)&Bs[k][tx * 8];
            *(float4*)&b[4] = *(const float4*)&Bs[k][tx * 8 + 4];
#pragma unroll
            for (int i = 0; i < 8; i++)
#pragma unroll
                for (int j = 0; j < 8; j++)
                    accm[i][j] += a[i] * b[j];
        }
        __syncthreads();
    }

    float bload[8];
    if (bias) {
        *(float4*)&bload[0] = *(const float4*)(bias + col0 + tx * 8);
        *(float4*)&bload[4] = *(const float4*)(bias + col0 + tx * 8 + 4);
    } else {
#pragma unroll
        for (int j = 0; j < 8; j++) bload[j] = 0.0f;
    }

#pragma unroll
    for (int i = 0; i < 8; i++) {
        int r = row0 + ty * 8 + i;
        int crow = cmap ? (((r & (NT - 1)) << 6) | (r >> 9)) : r;  // (t*64+b)
        float* cp = C + (size_t)crow * G3 + col0 + tx * 8;
        float4 v0, v1;
        v0.x = accm[i][0] + bload[0];
        v0.y = accm[i][1] + bload[1];
        v0.z = accm[i][2] + bload[2];
        v0.w = accm[i][3] + bload[3];
        v1.x = accm[i][4] + bload[4];
        v1.y = accm[i][5] + bload[5];
        v1.z = accm[i][6] + bload[6];
        v1.w = accm[i][7] + bload[7];
        if (acc) {
            float4 o0 = *(const float4*)cp;
            float4 o1 = *(const float4*)(cp + 4);
            v0.x += o0.x; v0.y += o0.y; v0.z += o0.z; v0.w += o0.w;
            v1.x += o1.x; v1.y += o1.y; v1.z += o1.z; v1.w += o1.w;
        }
        *(float4*)cp       = v0;
        *(float4*)(cp + 4) = v1;
    }
}

// ---------------- persistent recurrent scan ----------------
// grid = 128 CTAs x 256 threads. CTA c owns h columns {2c, 2c+1}.
// thread: b = tid&63, jj = (tid>>6)&1, kh = tid>>7  (K split in half).
// smem: ws[6][256] W_hh gate columns, hs = 256x64 XOR-swizzled h broadcast,
//       part = kh=1 partial sums.
#define SCAN_SMEM ((6*256 + 256*64 + 64*2*3) * 4)

__device__ __forceinline__ float sigmoidf_(float x) {
    return 1.0f / (1.0f + __expf(-x));
}

__global__ void __launch_bounds__(256, 1)
scan_kernel(const float* __restrict__ gi, const float* __restrict__ Whh,
            const float* __restrict__ bhh, const float* __restrict__ tau,
            float* __restrict__ out, int outc0, float* __restrict__ h1tm)
{
    extern __shared__ float smem[];
    float* ws   = smem;                    // 6*256
    float* hs   = ws + 6 * 256;            // 256*64 swizzled
    float* part = hs + 256 * 64;           // [64][2][3]

    const int c   = blockIdx.x;
    const int tid = threadIdx.x;
    const int b   = tid & 63;
    const int s   = tid >> 6;
    const int jj  = s & 1;
    const int kh  = s >> 1;                // 0 or 1
    const int col = 2 * c + jj;

    // load W_hh gate-column slices: ws[(g*2+j2)*256 + k] = W_hh[k][g*256 + 2c + j2]
    for (int i = tid; i < 6 * 256; i += 256) {
        int gj = i >> 8;
        int k  = i & 255;
        int g  = gj >> 1, j2 = gj & 1;
        ws[gj * 256 + k] = Whh[(size_t)k * G3 + g * H + 2 * c + j2];
    }

    const float invt = 1.0f / tau[0];
    const float br = bhh[col], bz = bhh[H + col], bn = bhh[2 * H + col];
    const float* wr = ws + (0 * 2 + jj) * 256 + kh * 128;
    const float* wz = ws + (1 * 2 + jj) * 256 + kh * 128;
    const float* wn = ws + (2 * 2 + jj) * 256 + kh * 128;
    const int kbase = kh * 128;

    for (int t = 0; t < NT; t++) {
        const float* hOld = g_hbuf[t & 1];
        float*       hNew = g_hbuf[(t & 1) ^ 1];

        // broadcast h_old into smem (coalesced global float4, swizzled scalar STS)
        {
            const float4* src = (const float4*)hOld;
#pragma unroll
            for (int n = 0; n < 16; n++) {
                int F = n * 256 + tid;            // 4096 float4 total
                float4 v = src[F];
                int bb  = F >> 6;
                int k0  = (F & 63) << 2;
                int bsw = bb ^ ((k0 >> 2) & 31);
                hs[(k0 + 0) * 64 + bsw] = v.x;
                hs[(k0 + 1) * 64 + bsw] = v.y;
                hs[(k0 + 2) * 64 + bsw] = v.z;
                hs[(k0 + 3) * 64 + bsw] = v.w;
            }
        }
        __syncthreads();

        // partial dot over this thread's K half
        float ar = 0.0f, az = 0.0f, an = 0.0f;
#pragma unroll 8
        for (int k4 = 0; k4 < 128; k4 += 4) {
            int bsw = b ^ (k4 >> 2);                 // ((kbase+k4)>>2)&31 == k4>>2
            const float* hp = hs + (kbase + k4) * 64 + bsw;
            float h0 = hp[0], h1v = hp[64], h2v = hp[128], h3v = hp[192];
            float4 r4 = *(const float4*)&wr[k4];
            float4 z4 = *(const float4*)&wz[k4];
            float4 n4 = *(const float4*)&wn[k4];
            ar += h0 * r4.x + h1v * r4.y + h2v * r4.z + h3v * r4.w;
            az += h0 * z4.x + h1v * z4.y + h2v * z4.z + h3v * z4.w;
            an += h0 * n4.x + h1v * n4.y + h2v * n4.z + h3v * n4.w;
        }

        if (kh) {
            float* p = part + (b * 2 + jj) * 3;
            p[0] = ar; p[1] = az; p[2] = an;
        }
        __syncthreads();

        if (!kh) {
            const float* p = part + (b * 2 + jj) * 3;
            ar += p[0]; az += p[1]; an += p[2];
            const float* gir = gi + ((size_t)t * 64 + b) * G3;
            float xr = gir[col], xz = gir[H + col], xn = gir[2 * H + col];
            float r = sigmoidf_(xr + ar + br);
            float z = sigmoidf_(xz + az + bz);
            float n = tanhf(xn + r * (an + bn));
            float hold = hs[col * 64 + (b ^ ((col >> 2) & 31))];
            float hc   = (1.0f - z) * n + z * hold;
            float hnew = hold + invt * (hc - hold);
            hNew[b * H + col] = hnew;
            out[((size_t)b * NT + t) * 512 + outc0 + col] = hnew;
            if (h1tm) h1tm[((size_t)t * 64 + b) * H + col] = hnew;
            __threadfence();
        }
        __syncthreads();

        // software grid barrier (gen-counter; double-buffered h => 1/step)
        if (tid == 0) {
            __threadfence();
            unsigned arrived = atomicAdd(&g_barcnt, 1u);
            unsigned want = (unsigned)(t + 1);
            if (arrived == NCTA - 1) {
                g_barcnt = 0u;
                __threadfence();
                g_bargen = want;
            } else {
                while (g_bargen < want) { }
                __threadfence();
            }
        }
        __syncthreads();
    }
}

// ---------------- launch ----------------
extern "C" void kernel_launch(void* const* d_in, const int* in_sizes, int n_in,
                              void* d_out, int out_size) {
    const float* x    = (const float*)d_in[0];
    const float* tau1 = (const float*)d_in[1];
    const float* tau2 = (const float*)d_in[2];
    const float* Wih1 = (const float*)d_in[3];
    const float* Whh1 = (const float*)d_in[4];
    const float* bih1 = (const float*)d_in[5];
    const float* bhh1 = (const float*)d_in[6];
    const float* Wih2 = (const float*)d_in[7];
    const float* Whh2 = (const float*)d_in[8];
    const float* bih2 = (const float*)d_in[9];
    const float* bhh2 = (const float*)d_in[10];
    float* out = (float*)d_out;

    float *gi1, *gi2, *h1tm;
    cudaGetSymbolAddress((void**)&gi1,  g_gi1);
    cudaGetSymbolAddress((void**)&gi2,  g_gi2);
    cudaGetSymbolAddress((void**)&h1tm, g_h1tm);

    cudaFuncSetAttribute(scan_kernel,
                         cudaFuncAttributeMaxDynamicSharedMemorySize, SCAN_SMEM);

    dim3 ggrid(G3 / BN, BT / BM);   // (6, 256)

    init_kernel<<<8, 256>>>();
    // gi1 = x @ W_ih1 + b_ih1   (time-major C)
    gemm_kernel<<<ggrid, 256>>>(x, D_IN, D_IN, Wih1, bih1, gi1, 0, 1);
    // gi2 = x @ W_ih2[:768] + b_ih2
    gemm_kernel<<<ggrid, 256>>>(x, D_IN, D_IN, Wih2, bih2, gi2, 0, 1);
    // cell-1 scan: writes out[:, :, 0:256] and h1 (time-major)
    scan_kernel<<<NCTA, 256, SCAN_SMEM>>>(gi1, Whh1, bhh1, tau1, out, 0, h1tm);
    init_kernel<<<8, 256>>>();
    // gi2 += h1 @ W_ih2[768:1024]
    gemm_kernel<<<ggrid, 256>>>(h1tm, H, H, Wih2 + (size_t)D_IN * G3, nullptr, gi2, 1, 0);
    // cell-2 scan: writes out[:, :, 256:512]
    scan_kernel<<<NCTA, 256, SCAN_SMEM>>>(gi2, Whh2, bhh2, tau2, out, 256, nullptr);
}

// round 7
// speedup vs baseline: 1.1245x; 1.1245x over previous
#include <cuda_runtime.h>
#include <cuda_bf16.h>
#include <math.h>
#include <stdint.h>

#define D_IN 768
#define H    256
#define NB   64
#define NT   512
#define BT   (NB*NT)    // 32768
#define G3   768        // 3*H
#define NCTA 128        // scan CTAs (single wave)

// ---------------- scratch (static device arrays: allowed) ----------------
__device__ float g_gi1[BT * (size_t)G3];                 // 96 MB, time-major rows (t*64+b)
__device__ float g_gi2[BT * (size_t)G3];                 // 96 MB
__device__ __nv_bfloat16 g_Abuf[BT * (size_t)(3*D_IN)];  // 144 MB [x_hi|x_lo|x_hi] time-major
__device__ __nv_bfloat16 g_A3[BT * (size_t)(3*H)];       // 48 MB  [h_hi|h_lo|h_hi] time-major
__device__ __nv_bfloat16 g_B1[(size_t)G3 * (3*D_IN)];    // W_ih1^T split-stacked
__device__ __nv_bfloat16 g_B2[(size_t)G3 * (3*D_IN)];    // W_ih2[:768]^T split-stacked
__device__ __nv_bfloat16 g_B3[(size_t)G3 * (3*H)];       // W_ih2[768:]^T split-stacked
__device__ float g_hbuf[2][NB * H];
__device__ unsigned g_barcnt;
__device__ volatile unsigned g_bargen;

// ---------------- helpers ----------------
__device__ __forceinline__ uint32_t smem_u32(const void* p) {
    uint32_t a;
    asm("{ .reg .u64 t; cvta.to.shared.u64 t, %1; cvt.u32.u64 %0, t; }" : "=r"(a) : "l"(p));
    return a;
}
__device__ __forceinline__ void ldsm_x4(uint32_t& r0, uint32_t& r1, uint32_t& r2, uint32_t& r3,
                                        uint32_t addr) {
    asm volatile("ldmatrix.sync.aligned.m8n8.x4.shared.b16 {%0,%1,%2,%3}, [%4];"
                 : "=r"(r0), "=r"(r1), "=r"(r2), "=r"(r3) : "r"(addr));
}
__device__ __forceinline__ void mma_bf16(float* c, const uint32_t* a, const uint32_t* b) {
    asm volatile("mma.sync.aligned.m16n8k16.row.col.f32.bf16.bf16.f32 "
                 "{%0,%1,%2,%3}, {%4,%5,%6,%7}, {%8,%9}, {%0,%1,%2,%3};"
                 : "+f"(c[0]), "+f"(c[1]), "+f"(c[2]), "+f"(c[3])
                 : "r"(a[0]), "r"(a[1]), "r"(a[2]), "r"(a[3]), "r"(b[0]), "r"(b[1]));
}
__device__ __forceinline__ void cp16(uint32_t dst, const void* src) {
    asm volatile("cp.async.cg.shared.global [%0], [%1], 16;" :: "r"(dst), "l"(src));
}
__device__ __forceinline__ void cp_commit() { asm volatile("cp.async.commit_group;"); }
__device__ __forceinline__ void cp_wait1()  { asm volatile("cp.async.wait_group 1;"); }

// swizzled byte offset inside a 128row x 32col bf16 tile (64B rows, 16B chunks)
__device__ __forceinline__ uint32_t sw_off(int row, int c) {
    return ((uint32_t)row << 6) + (((uint32_t)(c ^ ((row >> 1) & 3))) << 4);
}

// ---------------- init ----------------
__global__ void init_kernel() {
    int tid = blockIdx.x * blockDim.x + threadIdx.x;
    int nth = gridDim.x * blockDim.x;
    for (int i = tid; i < 2 * NB * H; i += nth)
        ((float*)g_hbuf)[i] = 0.0f;
    if (tid == 0) { g_barcnt = 0u; g_bargen = 0u; }
}

// ---------------- prep kernels ----------------
__global__ void prepA_kernel(const float* __restrict__ x, __nv_bfloat16* __restrict__ A) {
    long i = (long)blockIdx.x * blockDim.x + threadIdx.x;
    if (i >= (long)BT * D_IN) return;
    int k = (int)(i % D_IN);
    long row = i / D_IN;              // b*512 + t
    int b = (int)(row >> 9), t = (int)(row & 511);
    float v = x[i];
    __nv_bfloat16 hi = __float2bfloat16(v);
    __nv_bfloat16 lo = __float2bfloat16(v - __bfloat162float(hi));
    long orow = ((long)t * 64 + b) * (3 * D_IN);
    A[orow + k] = hi;
    A[orow + D_IN + k] = lo;
    A[orow + 2 * D_IN + k] = hi;
}

__global__ void prepB_kernel(const float* __restrict__ W, int Kin, __nv_bfloat16* __restrict__ Bm) {
    int i = blockIdx.x * blockDim.x + threadIdx.x;
    if (i >= G3 * Kin) return;
    int n = i / Kin, k = i % Kin;
    float v = W[(size_t)k * G3 + n];
    __nv_bfloat16 hi = __float2bfloat16(v);
    __nv_bfloat16 lo = __float2bfloat16(v - __bfloat162float(hi));
    size_t o = (size_t)n * (3 * Kin);
    Bm[o + k] = hi;
    Bm[o + Kin + k] = hi;
    Bm[o + 2 * Kin + k] = lo;
}

// ---------------- HMMA GEMM ----------------
// C[32768 x 768] (+=) A'[32768 x K] @ B'[768 x K]^T (+bias). 128x128 CTA tile.
// 8 warps, each 32(m) x 64(n). K-chunk 32, 2-stage cp.async pipeline.
__global__ void __launch_bounds__(256)
gemm_mma(const __nv_bfloat16* __restrict__ A, const __nv_bfloat16* __restrict__ Bm,
         int K, const float* __restrict__ bias, float* __restrict__ C, int acc)
{
    __shared__ __align__(1024) char smA[2][8192];
    __shared__ __align__(1024) char smB[2][8192];

    const int tid = threadIdx.x;
    const int wid = tid >> 5, lid = tid & 31;
    const int warp_m = wid & 3, warp_n = wid >> 2;
    const int m0 = blockIdx.y * 128, n0 = blockIdx.x * 128;

    const __nv_bfloat16* Ag = A + (size_t)m0 * K;
    const __nv_bfloat16* Bg = Bm + (size_t)n0 * K;

    const uint32_t sA[2] = { smem_u32(smA[0]), smem_u32(smA[1]) };
    const uint32_t sB[2] = { smem_u32(smB[0]), smem_u32(smB[1]) };

    // per-thread load slots
    const int lrow0 = tid >> 2;        // + 64
    const int lc    = tid & 3;
    const uint32_t loff0 = sw_off(lrow0, lc);
    const uint32_t loff1 = sw_off(lrow0 + 64, lc);

    float accf[2][8][4];
#pragma unroll
    for (int i = 0; i < 2; i++)
#pragma unroll
        for (int j = 0; j < 8; j++)
#pragma unroll
            for (int q = 0; q < 4; q++) accf[i][j][q] = 0.0f;

    const int nk = K >> 5;

    // prologue: stage 0
    {
        const char* ga0 = (const char*)(Ag + (size_t)lrow0 * K + lc * 8);
        const char* ga1 = (const char*)(Ag + (size_t)(lrow0 + 64) * K + lc * 8);
        const char* gb0 = (const char*)(Bg + (size_t)lrow0 * K + lc * 8);
        const char* gb1 = (const char*)(Bg + (size_t)(lrow0 + 64) * K + lc * 8);
        cp16(sA[0] + loff0, ga0); cp16(sA[0] + loff1, ga1);
        cp16(sB[0] + loff0, gb0); cp16(sB[0] + loff1, gb1);
        cp_commit();
    }

    // ldmatrix lane addressing (within a tile)
    const int a_row = (lid & 15);            // + m-frag base
    const int a_cd  = (lid >> 4);            // chunk delta
    const int b_row = (lid & 7) + ((lid >> 4) & 1) * 8;
    const int b_cd  = (lid >> 3) & 1;

    for (int kc = 0; kc < nk; kc++) {
        if (kc + 1 < nk) {
            int koff = (kc + 1) * 32;
            int st = (kc + 1) & 1;
            const char* ga0 = (const char*)(Ag + (size_t)lrow0 * K + koff + lc * 8);
            const char* ga1 = (const char*)(Ag + (size_t)(lrow0 + 64) * K + koff + lc * 8);
            const char* gb0 = (const char*)(Bg + (size_t)lrow0 * K + koff + lc * 8);
            const char* gb1 = (const char*)(Bg + (size_t)(lrow0 + 64) * K + koff + lc * 8);
            cp16(sA[st] + loff0, ga0); cp16(sA[st] + loff1, ga1);
            cp16(sB[st] + loff0, gb0); cp16(sB[st] + loff1, gb1);
        }
        cp_commit();
        cp_wait1();
        __syncthreads();

        const uint32_t aT = sA[kc & 1], bT = sB[kc & 1];
#pragma unroll
        for (int ks = 0; ks < 2; ks++) {
            uint32_t afr[2][4];
#pragma unroll
            for (int fm = 0; fm < 2; fm++) {
                int row = warp_m * 32 + fm * 16 + a_row;
                ldsm_x4(afr[fm][0], afr[fm][1], afr[fm][2], afr[fm][3],
                        aT + sw_off(row, 2 * ks + a_cd));
            }
            uint32_t bfr[8][2];
#pragma unroll
            for (int ng = 0; ng < 4; ng++) {
                int row = warp_n * 64 + ng * 16 + b_row;
                uint32_t r0, r1, r2, r3;
                ldsm_x4(r0, r1, r2, r3, bT + sw_off(row, 2 * ks + b_cd));
                bfr[ng * 2][0] = r0;     bfr[ng * 2][1] = r1;
                bfr[ng * 2 + 1][0] = r2; bfr[ng * 2 + 1][1] = r3;
            }
#pragma unroll
            for (int fm = 0; fm < 2; fm++)
#pragma unroll
                for (int fn = 0; fn < 8; fn++)
                    mma_bf16(accf[fm][fn], afr[fm], bfr[fn]);
        }
        __syncthreads();
    }

    // epilogue
#pragma unroll
    for (int fm = 0; fm < 2; fm++) {
        int row = m0 + warp_m * 32 + fm * 16 + (lid >> 2);
#pragma unroll
        for (int fn = 0; fn < 8; fn++) {
            int colg = n0 + warp_n * 64 + fn * 8 + (lid & 3) * 2;
            float2 v0 = make_float2(accf[fm][fn][0], accf[fm][fn][1]);
            float2 v1 = make_float2(accf[fm][fn][2], accf[fm][fn][3]);
            if (bias) {
                float b0 = bias[colg], b1 = bias[colg + 1];
                v0.x += b0; v0.y += b1; v1.x += b0; v1.y += b1;
            }
            float* p0 = C + (size_t)row * G3 + colg;
            float* p1 = C + (size_t)(row + 8) * G3 + colg;
            if (acc) {
                float2 o0 = *(const float2*)p0;
                float2 o1 = *(const float2*)p1;
                v0.x += o0.x; v0.y += o0.y; v1.x += o1.x; v1.y += o1.y;
            }
            *(float2*)p0 = v0;
            *(float2*)p1 = v1;
        }
    }
}

// ---------------- persistent recurrent scan ----------------
#define SCAN_SMEM ((6*256 + 256*64 + 64*2*3) * 4)

__device__ __forceinline__ float sigmoidf_(float x) {
    return 1.0f / (1.0f + __expf(-x));
}

__global__ void __launch_bounds__(256, 1)
scan_kernel(const float* __restrict__ gi, const float* __restrict__ Whh,
            const float* __restrict__ bhh, const float* __restrict__ tau,
            float* __restrict__ out, int outc0, __nv_bfloat16* __restrict__ a3)
{
    extern __shared__ float smem[];
    float* ws   = smem;                    // 6*256
    float* hs   = ws + 6 * 256;            // 256x64 swizzled
    float* part = hs + 256 * 64;           // [64][2][3]

    const int c   = blockIdx.x;
    const int tid = threadIdx.x;
    const int b   = tid & 63;
    const int s   = tid >> 6;
    const int jj  = s & 1;
    const int kh  = s >> 1;
    const int col = 2 * c + jj;

    for (int i = tid; i < 6 * 256; i += 256) {
        int gj = i >> 8;
        int k  = i & 255;
        int g  = gj >> 1, j2 = gj & 1;
        ws[gj * 256 + k] = Whh[(size_t)k * G3 + g * H + 2 * c + j2];
    }

    const float invt = 1.0f / tau[0];
    const float br = bhh[col], bz = bhh[H + col], bn = bhh[2 * H + col];
    const float* wr = ws + (0 * 2 + jj) * 256 + kh * 128;
    const float* wz = ws + (1 * 2 + jj) * 256 + kh * 128;
    const float* wn = ws + (2 * 2 + jj) * 256 + kh * 128;
    const int kbase = kh * 128;

    for (int t = 0; t < NT; t++) {
        const float* hOld = g_hbuf[t & 1];
        float*       hNew = g_hbuf[(t & 1) ^ 1];

        {
            const float4* src = (const float4*)hOld;
#pragma unroll
            for (int n = 0; n < 16; n++) {
                int F = n * 256 + tid;
                float4 v = src[F];
                int bb  = F >> 6;
                int k0  = (F & 63) << 2;
                int bsw = bb ^ ((k0 >> 2) & 31);
                hs[(k0 + 0) * 64 + bsw] = v.x;
                hs[(k0 + 1) * 64 + bsw] = v.y;
                hs[(k0 + 2) * 64 + bsw] = v.z;
                hs[(k0 + 3) * 64 + bsw] = v.w;
            }
        }
        __syncthreads();

        float ar = 0.0f, az = 0.0f, an = 0.0f;
#pragma unroll 8
        for (int k4 = 0; k4 < 128; k4 += 4) {
            int bsw = b ^ (k4 >> 2);
            const float* hp = hs + (kbase + k4) * 64 + bsw;
            float h0 = hp[0], h1v = hp[64], h2v = hp[128], h3v = hp[192];
            float4 r4 = *(const float4*)&wr[k4];
            float4 z4 = *(const float4*)&wz[k4];
            float4 n4 = *(const float4*)&wn[k4];
            ar += h0 * r4.x + h1v * r4.y + h2v * r4.z + h3v * r4.w;
            az += h0 * z4.x + h1v * z4.y + h2v * z4.z + h3v * z4.w;
            an += h0 * n4.x + h1v * n4.y + h2v * n4.z + h3v * n4.w;
        }

        if (kh) {
            float* p = part + (b * 2 + jj) * 3;
            p[0] = ar; p[1] = az; p[2] = an;
        }
        __syncthreads();

        if (!kh) {
            const float* p = part + (b * 2 + jj) * 3;
            ar += p[0]; az += p[1]; an += p[2];
            const float* gir = gi + ((size_t)t * 64 + b) * G3;
            float xr = gir[col], xz = gir[H + col], xn = gir[2 * H + col];
            float r = sigmoidf_(xr + ar + br);
            float z = sigmoidf_(xz + az + bz);
            float n = tanhf(xn + r * (an + bn));
            float hold = hs[col * 64 + (b ^ ((col >> 2) & 31))];
            float hc   = (1.0f - z) * n + z * hold;
            float hnew = hold + invt * (hc - hold);
            hNew[b * H + col] = hnew;
            out[((size_t)b * NT + t) * 512 + outc0 + col] = hnew;
            if (a3) {
                size_t ro = ((size_t)t * 64 + b) * (3 * H);
                __nv_bfloat16 hi = __float2bfloat16(hnew);
                __nv_bfloat16 lo = __float2bfloat16(hnew - __bfloat162float(hi));
                a3[ro + col] = hi;
                a3[ro + H + col] = lo;
                a3[ro + 2 * H + col] = hi;
            }
            __threadfence();
        }
        __syncthreads();

        if (tid == 0) {
            __threadfence();
            unsigned arrived = atomicAdd(&g_barcnt, 1u);
            unsigned want = (unsigned)(t + 1);
            if (arrived == NCTA - 1) {
                g_barcnt = 0u;
                __threadfence();
                g_bargen = want;
            } else {
                while (g_bargen < want) { }
                __threadfence();
            }
        }
        __syncthreads();
    }
}

// ---------------- launch ----------------
extern "C" void kernel_launch(void* const* d_in, const int* in_sizes, int n_in,
                              void* d_out, int out_size) {
    const float* x    = (const float*)d_in[0];
    const float* tau1 = (const float*)d_in[1];
    const float* tau2 = (const float*)d_in[2];
    const float* Wih1 = (const float*)d_in[3];
    const float* Whh1 = (const float*)d_in[4];
    const float* bih1 = (const float*)d_in[5];
    const float* bhh1 = (const float*)d_in[6];
    const float* Wih2 = (const float*)d_in[7];
    const float* Whh2 = (const float*)d_in[8];
    const float* bih2 = (const float*)d_in[9];
    const float* bhh2 = (const float*)d_in[10];
    float* out = (float*)d_out;

    float *gi1, *gi2;
    __nv_bfloat16 *Ab, *A3, *B1, *B2, *B3;
    cudaGetSymbolAddress((void**)&gi1, g_gi1);
    cudaGetSymbolAddress((void**)&gi2, g_gi2);
    cudaGetSymbolAddress((void**)&Ab,  g_Abuf);
    cudaGetSymbolAddress((void**)&A3,  g_A3);
    cudaGetSymbolAddress((void**)&B1,  g_B1);
    cudaGetSymbolAddress((void**)&B2,  g_B2);
    cudaGetSymbolAddress((void**)&B3,  g_B3);

    cudaFuncSetAttribute(scan_kernel,
                         cudaFuncAttributeMaxDynamicSharedMemorySize, SCAN_SMEM);

    dim3 ggrid(G3 / 128, BT / 128);   // (6, 256)

    init_kernel<<<8, 256>>>();
    prepA_kernel<<<(int)(((long)BT * D_IN + 255) / 256), 256>>>(x, Ab);
    prepB_kernel<<<(G3 * D_IN + 255) / 256, 256>>>(Wih1, D_IN, B1);
    prepB_kernel<<<(G3 * D_IN + 255) / 256, 256>>>(Wih2, D_IN, B2);
    prepB_kernel<<<(G3 * H + 255) / 256, 256>>>(Wih2 + (size_t)D_IN * G3, H, B3);

    // gi1 = x @ W_ih1 + b_ih1 ; gi2 = x @ W_ih2[:768] + b_ih2   (split-bf16 HMMA)
    gemm_mma<<<ggrid, 256>>>(Ab, B1, 3 * D_IN, bih1, gi1, 0);
    gemm_mma<<<ggrid, 256>>>(Ab, B2, 3 * D_IN, bih2, gi2, 0);

    // cell-1 scan: writes out[:, :, 0:256] and split-bf16 h1 triple
    scan_kernel<<<NCTA, 256, SCAN_SMEM>>>(gi1, Whh1, bhh1, tau1, out, 0, A3);

    init_kernel<<<8, 256>>>();
    // gi2 += h1 @ W_ih2[768:1024]
    gemm_mma<<<ggrid, 256>>>(A3, B3, 3 * H, nullptr, gi2, 1);

    // cell-2 scan: writes out[:, :, 256:512]
    scan_kernel<<<NCTA, 256, SCAN_SMEM>>>(gi2, Whh2, bhh2, tau2, out, 256, nullptr);
}